// round 3
// baseline (speedup 1.0000x reference)
#include <cuda_runtime.h>

#define D_DIM   512
#define H1_DIM  128
#define H2_DIM  64
#define B_DIM   2048
#define N_NODES 20000
#define N_DRUG  2000

typedef unsigned long long ull;

__device__ __forceinline__ ull pack2s(float x) {            // {x, x}
    ull r; asm("mov.b64 %0, {%1, %1};" : "=l"(r) : "f"(x)); return r;
}
__device__ __forceinline__ void ffma2(ull& d, ull a, ull b) { // d += a*b (2-lane)
    asm("fma.rn.f32x2 %0, %1, %2, %3;" : "=l"(d) : "l"(a), "l"(b), "l"(d));
}
__device__ __forceinline__ float2 unpk(ull v) {
    float2 f; asm("mov.b64 {%0, %1}, %2;" : "=f"(f.x), "=f"(f.y) : "l"(v)); return f;
}

// Scratch: layer-1 partial products
__device__ float g_Ptop[N_DRUG  * H1_DIM];   // embed[:2000]  @ W1[0:512]
__device__ float g_Pbot[N_NODES * H1_DIM];   // embed[:20000] @ W1[512:1024]

// ---------------------------------------------------------------------------
// Kernel 1: P[r][o] = sum_d embed[r][d] * W1[woff+d][o]
// 64x128 tile, BK=16, 256 threads, 8x4 FFMA2 micro-tile.
// Double-buffered smem + register prefetch: one barrier per k-tile, LDG for
// tile t+1 in flight during compute of tile t.
// ---------------------------------------------------------------------------
#define AS_STRIDE 68

__global__ void __launch_bounds__(256, 3) gemm1_kernel(const float* __restrict__ embed,
                                                       const float* __restrict__ W1) {
    const int NBOT = (N_NODES + 63) / 64;   // 313
    int bx = blockIdx.x;
    int woff, M;
    float* P;
    if (bx < NBOT) { woff = D_DIM; M = N_NODES; P = g_Pbot; }
    else           { bx -= NBOT; woff = 0; M = N_DRUG; P = g_Ptop; }
    const int row0 = bx * 64;

    __shared__ float As[2][16 * AS_STRIDE];   // k-major [16][64(+pad)]
    __shared__ float Bs[2][16 * 128];         // k-major [16][128]

    const int tid = threadIdx.x;
    const int tx = tid & 31;        // 32 col-groups of 4
    const int ty = tid >> 5;        // 8 row-groups of 8 (warp-uniform)

    ull acc[8][2];
#pragma unroll
    for (int i = 0; i < 8; i++) { acc[i][0] = 0ull; acc[i][1] = 0ull; }

    const int ar = tid >> 2;              // 0..63
    const int ac = (tid & 3) << 2;        // 0,4,8,12
    const int agr = min(row0 + ar, M - 1);
    const float* aptr  = embed + agr * D_DIM + ac;
    const float* bptr0 = W1 + (woff + ty)     * H1_DIM + (tx << 2);
    const float* bptr1 = W1 + (woff + ty + 8) * H1_DIM + (tx << 2);

    // prologue: fetch tile 0, stage into buf 0
    float4 a_reg = *(const float4*)(aptr);
    float4 b_reg0 = *(const float4*)(bptr0);
    float4 b_reg1 = *(const float4*)(bptr1);
    {
        As[0][(ac + 0) * AS_STRIDE + ar] = a_reg.x;
        As[0][(ac + 1) * AS_STRIDE + ar] = a_reg.y;
        As[0][(ac + 2) * AS_STRIDE + ar] = a_reg.z;
        As[0][(ac + 3) * AS_STRIDE + ar] = a_reg.w;
        *(float4*)&Bs[0][ty * 128 + (tx << 2)]       = b_reg0;
        *(float4*)&Bs[0][(ty + 8) * 128 + (tx << 2)] = b_reg1;
    }
    __syncthreads();

#pragma unroll 2
    for (int t = 0; t < 32; t++) {
        const int cur = t & 1;
        const int nxt = cur ^ 1;
        if (t < 31) {   // prefetch next tile into registers (overlaps compute)
            int k0 = (t + 1) * 16;
            a_reg  = *(const float4*)(aptr + k0);
            b_reg0 = *(const float4*)(bptr0 + k0 * H1_DIM);
            b_reg1 = *(const float4*)(bptr1 + k0 * H1_DIM);
        }
#pragma unroll
        for (int k = 0; k < 16; k++) {
            const float4 a0 = *(const float4*)&As[cur][k * AS_STRIDE + ty * 8];
            const float4 a1 = *(const float4*)&As[cur][k * AS_STRIDE + ty * 8 + 4];
            const ulonglong2 bb = *(const ulonglong2*)&Bs[cur][k * 128 + (tx << 2)];
            ull ap[8];
            ap[0] = pack2s(a0.x); ap[1] = pack2s(a0.y);
            ap[2] = pack2s(a0.z); ap[3] = pack2s(a0.w);
            ap[4] = pack2s(a1.x); ap[5] = pack2s(a1.y);
            ap[6] = pack2s(a1.z); ap[7] = pack2s(a1.w);
#pragma unroll
            for (int i = 0; i < 8; i++) {
                ffma2(acc[i][0], ap[i], bb.x);
                ffma2(acc[i][1], ap[i], bb.y);
            }
        }
        if (t < 31) {   // stage next tile into the other buffer
            As[nxt][(ac + 0) * AS_STRIDE + ar] = a_reg.x;
            As[nxt][(ac + 1) * AS_STRIDE + ar] = a_reg.y;
            As[nxt][(ac + 2) * AS_STRIDE + ar] = a_reg.z;
            As[nxt][(ac + 3) * AS_STRIDE + ar] = a_reg.w;
            *(float4*)&Bs[nxt][ty * 128 + (tx << 2)]       = b_reg0;
            *(float4*)&Bs[nxt][(ty + 8) * 128 + (tx << 2)] = b_reg1;
            __syncthreads();
        }
    }

#pragma unroll
    for (int i = 0; i < 8; i++) {
        int r = row0 + ty * 8 + i;
        if (r < M) {
            float2 c01 = unpk(acc[i][0]);
            float2 c23 = unpk(acc[i][1]);
            *(float4*)&P[r * H1_DIM + (tx << 2)] =
                make_float4(c01.x, c01.y, c23.x, c23.y);
        }
    }
}

// ---------------------------------------------------------------------------
// Kernel 2: 128 samples/block, 256 threads, 8x4 FFMA2 micro-tile.
// K-split: X1 held as a 64-col half (34.8KB) -> smem 68.5KB -> 3 blocks/SM.
// ---------------------------------------------------------------------------
#define NSAMP 128
#define X1_STRIDE 68
#define SMEM2_BYTES ((NSAMP * X1_STRIDE + 128 * 64 + 128 + 64 + 64 + 3 * NSAMP) * 4)

__global__ void __launch_bounds__(256, 3) mlp2_kernel(
    const int* __restrict__ h, const int* __restrict__ t, const int* __restrict__ ns,
    const float* __restrict__ b1, const float* __restrict__ W2,
    const float* __restrict__ b2, const float* __restrict__ W3,
    const float* __restrict__ b3, float* __restrict__ out)
{
    extern __shared__ float smem[];
    float* X1  = smem;                       // [128][68] (current 64-k half)
    float* W2s = X1 + NSAMP * X1_STRIDE;     // [128][64] k-major (full)
    float* b1s = W2s + 128 * 64;             // [128]
    float* b2s = b1s + 128;                  // [64]
    float* W3s = b2s + 64;                   // [64]
    int* sTop = (int*)(W3s + 64);            // [128]
    int* sBot = sTop + NSAMP;                // [128]
    int* sOut = sBot + NSAMP;                // [128]

    const int tid = threadIdx.x;

    // ---- phase 0: decode sample indices + stage small tensors ----
    if (tid < NSAMP) {
        int S = blockIdx.x * NSAMP + tid;
        int b = S / 65;
        int r = S - b * 65;
        int itop, jbot, oaddr;
        if (r == 64)      { itop = h[b];           jbot = t[b];           oaddr = b; }
        else if (r < 32)  { itop = h[b];           jbot = ns[b * 64 + r]; oaddr = B_DIM + b * 64 + r; }
        else              { itop = ns[b * 64 + r]; jbot = t[b];           oaddr = B_DIM + b * 64 + r; }
        sTop[tid] = itop; sBot[tid] = jbot; sOut[tid] = oaddr;
    }
#pragma unroll
    for (int i = tid; i < 2048; i += 256)   // W2: 2048 float4
        ((float4*)W2s)[i] = ((const float4*)W2)[i];
    if (tid < 128) b1s[tid] = b1[tid];
    if (tid < 64) { b2s[tid] = b2[tid]; W3s[tid] = W3[tid]; }
    __syncthreads();

    const int tx = tid & 15;   // cols 4tx..4tx+3
    const int ty = tid >> 4;   // samples 8ty..8ty+7

    ull acc[8][2];
#pragma unroll
    for (int i = 0; i < 8; i++) { acc[i][0] = 0ull; acc[i][1] = 0ull; }

#pragma unroll
    for (int half = 0; half < 2; half++) {
        const int koff = half * 64;

        // ---- phase 1: X1[s][0:64] = relu(Ptop[i][koff:] + Pbot[j][koff:] + b1) ----
        {
            const int lane = tid & 31;
            const int wid = tid >> 5;
            const int fi = (lane & 15) << 2;  // float4 col within half
            const int sp = lane >> 4;         // sample parity
            float4 vb1 = *(const float4*)&b1s[koff + fi];
#pragma unroll
            for (int it = 0; it < 8; it++) {
                int s = it * 16 + wid * 2 + sp;
                int i = sTop[s], j = sBot[s];
                float4 pa = *(const float4*)&g_Ptop[i * H1_DIM + koff + fi];
                float4 pb = *(const float4*)&g_Pbot[j * H1_DIM + koff + fi];
                float4 x;
                x.x = fmaxf(pa.x + pb.x + vb1.x, 0.f);
                x.y = fmaxf(pa.y + pb.y + vb1.y, 0.f);
                x.z = fmaxf(pa.z + pb.z + vb1.z, 0.f);
                x.w = fmaxf(pa.w + pb.w + vb1.w, 0.f);
                *(float4*)&X1[s * X1_STRIDE + fi] = x;
            }
        }
        __syncthreads();

        // ---- phase 2: acc += X1half @ W2[koff:koff+64, :] ----
#pragma unroll 2
        for (int kq = 0; kq < 16; kq++) {
            float4 xa[8];
#pragma unroll
            for (int si = 0; si < 8; si++)
                xa[si] = *(const float4*)&X1[(8 * ty + si) * X1_STRIDE + (kq << 2)];
#pragma unroll
            for (int kk = 0; kk < 4; kk++) {
                const ulonglong2 w =
                    *(const ulonglong2*)&W2s[(koff + (kq << 2) + kk) * H2_DIM + (tx << 2)];
#pragma unroll
                for (int si = 0; si < 8; si++) {
                    float x = (kk == 0) ? xa[si].x : (kk == 1) ? xa[si].y
                            : (kk == 2) ? xa[si].z : xa[si].w;
                    ull xp = pack2s(x);
                    ffma2(acc[si][0], xp, w.x);
                    ffma2(acc[si][1], xp, w.y);
                }
            }
        }
        __syncthreads();   // before next half overwrites X1
    }

    // ---- phase 3: layer 3 + reduction over 16 tx groups ----
    float4 b2r = *(const float4*)&b2s[tx << 2];
    float4 w3r = *(const float4*)&W3s[tx << 2];
    const float b3v = b3[0];

#pragma unroll
    for (int si = 0; si < 8; si++) {
        float2 c01 = unpk(acc[si][0]);
        float2 c23 = unpk(acc[si][1]);
        float p = 0.f, v;
        v = fmaxf(c01.x + b2r.x, 0.f); p = fmaf(v, w3r.x, p);
        v = fmaxf(c01.y + b2r.y, 0.f); p = fmaf(v, w3r.y, p);
        v = fmaxf(c23.x + b2r.z, 0.f); p = fmaf(v, w3r.z, p);
        v = fmaxf(c23.y + b2r.w, 0.f); p = fmaf(v, w3r.w, p);
#pragma unroll
        for (int m = 8; m > 0; m >>= 1)
            p += __shfl_xor_sync(0xffffffffu, p, m, 16);
        if (tx == 0)
            out[sOut[8 * ty + si]] = p + b3v;
    }
}

// ---------------------------------------------------------------------------
extern "C" void kernel_launch(void* const* d_in, const int* in_sizes, int n_in,
                              void* d_out, int out_size) {
    const float* embed = (const float*)d_in[0];
    const float* W1    = (const float*)d_in[1];
    const float* b1    = (const float*)d_in[2];
    const float* W2    = (const float*)d_in[3];
    const float* b2    = (const float*)d_in[4];
    const float* W3    = (const float*)d_in[5];
    const float* b3    = (const float*)d_in[6];
    const int*   h     = (const int*)d_in[7];
    const int*   t     = (const int*)d_in[8];
    const int*   ns    = (const int*)d_in[9];
    float* out = (float*)d_out;

    const int NBOT = (N_NODES + 63) / 64;   // 313
    const int NTOP = (N_DRUG  + 63) / 64;   // 32
    gemm1_kernel<<<NBOT + NTOP, 256>>>(embed, W1);

    cudaFuncSetAttribute(mlp2_kernel, cudaFuncAttributeMaxDynamicSharedMemorySize,
                         SMEM2_BYTES);
    mlp2_kernel<<<(B_DIM * 65) / NSAMP, 256, SMEM2_BYTES>>>(h, t, ns, b1, W2, b2, W3, b3, out);
}